// round 16
// baseline (speedup 1.0000x reference)
#include <cuda_runtime.h>
#include <math.h>

// ---------------- problem constants (fixed by the dataset) ----------------
#define NMEAS   5120        // n
#define NTOT    16384       // N
#define BATCH   500
#define LDP     512         // padded batch leading dim for scratch
#define LSEC    512         // number of sections
#define MSEC    32          // section size
#define SIGMA2  0.2f
#define SCALE_C 3.1622776601683795f   // sqrt(n*P/L) = sqrt(10)
#define MAXITR  4

// ---------------- scratch (static device memory; no allocations) ----------
__device__ float g_y[(size_t)NMEAS * LDP];       // y = A x + noise
__device__ float g_t[(size_t)NMEAS * LDP];       // residual
__device__ float g_s[(size_t)NTOT  * LDP];       // current estimate (padded)
__device__ float g_r[(size_t)NTOT  * LDP];       // r = s + g W t
__device__ float g_x[(size_t)NTOT  * LDP];       // padded x
__device__ float g_noise[(size_t)NMEAS * LDP];   // padded noise
__device__ float g_taa;                          // sum(A*A) == sum(W*W)
__device__ float g_part[1024];                   // taa partials
__device__ float g_colpart[10 * LDP];            // per-row-chunk column partials of ||t||^2
__device__ float g_tau2[LDP];                    // per-batch tau^2

// ---------------- pad [rows, BATCH] -> [rows, LDP] -------------------------
__global__ void pad_kernel(const float* __restrict__ src, float* __restrict__ dst,
                           int rows) {
    size_t idx = (size_t)blockIdx.x * blockDim.x + threadIdx.x;
    if (idx >= (size_t)rows * LDP) return;
    int j = (int)(idx >> 9);
    int b = (int)(idx & 511);
    dst[idx] = (b < BATCH) ? src[(size_t)j * BATCH + b] : 0.0f;
}

// ---------------- taa = sum(A*A), deterministic two-pass -------------------
__global__ void taa_partial_kernel(const float* __restrict__ A) {
    const size_t n4 = (size_t)NMEAS * NTOT / 4;
    float s = 0.0f;
    for (size_t i = (size_t)blockIdx.x * blockDim.x + threadIdx.x; i < n4;
         i += (size_t)gridDim.x * blockDim.x) {
        float4 v = ((const float4*)A)[i];
        s += v.x * v.x + v.y * v.y + v.z * v.z + v.w * v.w;
    }
    __shared__ float sh[256];
    sh[threadIdx.x] = s;
    __syncthreads();
    for (int o = 128; o > 0; o >>= 1) {
        if (threadIdx.x < o) sh[threadIdx.x] += sh[threadIdx.x + o];
        __syncthreads();
    }
    if (threadIdx.x == 0) g_part[blockIdx.x] = sh[0];
}

__global__ void taa_final_kernel() {
    __shared__ float sh[1024];
    sh[threadIdx.x] = g_part[threadIdx.x];
    __syncthreads();
    for (int o = 512; o > 0; o >>= 1) {
        if (threadIdx.x < o) sh[threadIdx.x] += sh[threadIdx.x + o];
        __syncthreads();
    }
    if (threadIdx.x == 0) g_taa = sh[0];
}

// ---------------- GEMM: C[M,512] = epilogue(A[M,K] * B[K,512]) -------------
// All B/C/E operands are padded to LDP=512 columns -> no bounds checks.
// MODE 0: C = acc + E            (y = A x + noise)
// MODE 1: C = E - acc            (t = y - A s)
// MODE 2: C = E + gamma[gi]*acc  (r = s + g * W t)
// BM=BN=128, BK=8, 256 threads, 8x8 micro-tile, double-buffered smem.
template <int MODE>
__global__ __launch_bounds__(256, 2) void gemm128_kernel(
    const float* __restrict__ Aop, int lda,
    const float* __restrict__ Bop,
    float*       __restrict__ Cop,
    const float* __restrict__ Eop,
    const float* __restrict__ gamma, int gi, int K)
{
    __shared__ float As[2][8][132];   // transposed A tile, padded row (no STS conflicts)
    __shared__ float Bs[2][8][128];

    const int tid = threadIdx.x;
    const int bm0 = blockIdx.y * 128;
    const int bn0 = blockIdx.x * 128;
    const int tx = tid & 15;          // output col group (8 cols)
    const int ty = tid >> 4;          // output row group (8 rows)

    // A loader: 128 rows x 8 k -> each thread one float4 along k
    const int ar = tid >> 1;          // 0..127
    const int ac = (tid & 1) * 4;     // 0 or 4
    // B loader: 8 k-rows x 128 cols -> each thread one float4 along cols
    const int br = tid >> 5;          // 0..7
    const int bc = (tid & 31) * 4;    // 0..124

    const float* Ap = Aop + (size_t)(bm0 + ar) * lda + ac;
    const float* Bp = Bop + (size_t)br * LDP + bn0 + bc;

    float acc[8][8];
#pragma unroll
    for (int i = 0; i < 8; i++)
#pragma unroll
        for (int j = 0; j < 8; j++) acc[i][j] = 0.0f;

    // prologue: tile 0 -> buffer 0
    float4 a = *(const float4*)Ap;
    float4 b = *(const float4*)Bp;
    As[0][ac + 0][ar] = a.x;
    As[0][ac + 1][ar] = a.y;
    As[0][ac + 2][ar] = a.z;
    As[0][ac + 3][ar] = a.w;
    *(float4*)&Bs[0][br][bc] = b;
    __syncthreads();

    int buf = 0;
    for (int k0 = 8; k0 <= K; k0 += 8) {
        if (k0 < K) {   // stage next tile into registers
            a = *(const float4*)(Ap + k0);
            b = *(const float4*)(Bp + (size_t)k0 * LDP);
        }
#pragma unroll
        for (int k = 0; k < 8; k++) {
            float4 av0 = *(const float4*)&As[buf][k][ty * 8];
            float4 av1 = *(const float4*)&As[buf][k][ty * 8 + 4];
            float4 bv0 = *(const float4*)&Bs[buf][k][tx * 8];
            float4 bv1 = *(const float4*)&Bs[buf][k][tx * 8 + 4];
            float aa[8] = {av0.x, av0.y, av0.z, av0.w, av1.x, av1.y, av1.z, av1.w};
            float bb[8] = {bv0.x, bv0.y, bv0.z, bv0.w, bv1.x, bv1.y, bv1.z, bv1.w};
#pragma unroll
            for (int i = 0; i < 8; i++)
#pragma unroll
                for (int j = 0; j < 8; j++)
                    acc[i][j] = fmaf(aa[i], bb[j], acc[i][j]);
        }
        if (k0 < K) {
            buf ^= 1;
            As[buf][ac + 0][ar] = a.x;
            As[buf][ac + 1][ar] = a.y;
            As[buf][ac + 2][ar] = a.z;
            As[buf][ac + 3][ar] = a.w;
            *(float4*)&Bs[buf][br][bc] = b;
            __syncthreads();
        }
    }

    const float g = (MODE == 2) ? gamma[gi] : 0.0f;

#pragma unroll
    for (int i = 0; i < 8; i++) {
        const size_t m = (size_t)(bm0 + ty * 8 + i);
#pragma unroll
        for (int jj = 0; jj < 8; jj += 4) {
            const size_t off = m * LDP + bn0 + tx * 8 + jj;
            float4 e = *(const float4*)(Eop + off);
            float4 o;
            if (MODE == 0) {
                o.x = acc[i][jj + 0] + e.x;
                o.y = acc[i][jj + 1] + e.y;
                o.z = acc[i][jj + 2] + e.z;
                o.w = acc[i][jj + 3] + e.w;
            } else if (MODE == 1) {
                o.x = e.x - acc[i][jj + 0];
                o.y = e.y - acc[i][jj + 1];
                o.z = e.z - acc[i][jj + 2];
                o.w = e.w - acc[i][jj + 3];
            } else {
                o.x = fmaf(g, acc[i][jj + 0], e.x);
                o.y = fmaf(g, acc[i][jj + 1], e.y);
                o.z = fmaf(g, acc[i][jj + 2], e.z);
                o.w = fmaf(g, acc[i][jj + 3], e.w);
            }
            *(float4*)(Cop + off) = o;
        }
    }
}

// ---------------- column ||t||^2 partials, deterministic -------------------
// grid (8 col-tiles of 64, 10 row-chunks of 512), 256 threads = 64 cols x 4 lanes
__global__ void col_partial_kernel() {
    const int c    = blockIdx.x * 64 + (threadIdx.x & 63);
    const int lane = threadIdx.x >> 6;     // 0..3
    const int r0   = blockIdx.y * 512;
    float s = 0.0f;
    for (int i = lane; i < 512; i += 4) {
        float v = g_t[(size_t)(r0 + i) * LDP + c];
        s += v * v;
    }
    __shared__ float sh[4][64];
    sh[lane][threadIdx.x & 63] = s;
    __syncthreads();
    if (lane == 0) {
        int cc = threadIdx.x & 63;
        g_colpart[(size_t)blockIdx.y * LDP + c] =
            sh[0][cc] + sh[1][cc] + sh[2][cc] + sh[3][cc];
    }
}

// ---------------- tau2 per batch column ------------------------------------
__global__ void tau2_kernel(const float* __restrict__ gamma, int gi) {
    const int c = threadIdx.x;   // 0..511
    float cs = 0.0f;
#pragma unroll
    for (int j = 0; j < 10; j++) cs += g_colpart[(size_t)j * LDP + c];
    const float taa = g_taa;
    const float v2  = (cs - (float)MSEC * SIGMA2) / taa;
    const float g   = gamma[gi];
    const float Nf  = (float)NTOT;
    const float tau2 = v2 / Nf * (Nf + (g * g - 2.0f * g) * (float)MSEC)
                     + g * g * taa * SIGMA2 / Nf;   // tww == taa (W = A^T)
    g_tau2[c] = tau2;
}

// ---------------- shrink: per-section softmax ------------------------------
// grid (4 col-chunks of 128, 512 sections), 128 threads
__global__ void shrink_kernel(float* __restrict__ out, int ldo) {
    const int c = blockIdx.x * 128 + threadIdx.x;
    if (c >= BATCH) return;
    const int l = blockIdx.y;
    const float inv = SCALE_C / g_tau2[c];
    float v[MSEC];
    float mx = -1e30f;
#pragma unroll
    for (int m = 0; m < MSEC; m++) {
        v[m] = g_r[(size_t)(l * MSEC + m) * LDP + c] * inv;
        mx = fmaxf(mx, v[m]);
    }
    float sum = 0.0f;
#pragma unroll
    for (int m = 0; m < MSEC; m++) {
        v[m] = expf(v[m] - mx);
        sum += v[m];
    }
    const float is = 1.0f / sum;
#pragma unroll
    for (int m = 0; m < MSEC; m++) {
        out[(size_t)(l * MSEC + m) * ldo + c] = v[m] * is;
    }
}

// ---------------- host driver ----------------------------------------------
extern "C" void kernel_launch(void* const* d_in, const int* in_sizes, int n_in,
                              void* d_out, int out_size) {
    const float* x     = (const float*)d_in[0];   // [N, B]
    const float* s_in  = (const float*)d_in[1];   // [N, B]
    const float* noise = (const float*)d_in[2];   // [n, B]
    const float* A     = (const float*)d_in[3];   // [n, N]
    const float* W     = (const float*)d_in[4];   // [N, n] (== A^T)
    const float* gamma = (const float*)d_in[5];   // [4]
    float* out = (float*)d_out;                   // [N, B]
    (void)in_sizes; (void)n_in; (void)out_size;   // max_itr (d_in[6]) fixed = 4

    float *yb, *tb, *sb, *rb, *xb, *nb;
    cudaGetSymbolAddress((void**)&yb, g_y);
    cudaGetSymbolAddress((void**)&tb, g_t);
    cudaGetSymbolAddress((void**)&sb, g_s);
    cudaGetSymbolAddress((void**)&rb, g_r);
    cudaGetSymbolAddress((void**)&xb, g_x);
    cudaGetSymbolAddress((void**)&nb, g_noise);

    // pad s, x, noise into 512-wide scratch (zero pad columns)
    {
        size_t tN = (size_t)NTOT * LDP;
        size_t tn = (size_t)NMEAS * LDP;
        pad_kernel<<<(unsigned)((tN + 255) / 256), 256>>>(s_in, sb, NTOT);
        pad_kernel<<<(unsigned)((tN + 255) / 256), 256>>>(x, xb, NTOT);
        pad_kernel<<<(unsigned)((tn + 255) / 256), 256>>>(noise, nb, NMEAS);
    }
    // taa
    taa_partial_kernel<<<1024, 256>>>(A);
    taa_final_kernel<<<1, 1024>>>();

    // y = A x + noise
    gemm128_kernel<0><<<dim3(4, NMEAS / 128), 256>>>(
        A, NTOT, xb, yb, nb, nullptr, 0, NTOT);

    for (int i = 0; i < MAXITR; i++) {
        // t = y - A s
        gemm128_kernel<1><<<dim3(4, NMEAS / 128), 256>>>(
            A, NTOT, sb, tb, yb, nullptr, 0, NTOT);
        // tau2 from ||t||^2 columns
        col_partial_kernel<<<dim3(8, 10), 256>>>();
        tau2_kernel<<<1, 512>>>(gamma, i);
        // r = s + gamma[i] * (W t)
        gemm128_kernel<2><<<dim3(4, NTOT / 128), 256>>>(
            W, NMEAS, tb, rb, sb, gamma, i, NMEAS);
        // s = shrink(r, tau2)
        if (i == MAXITR - 1)
            shrink_kernel<<<dim3(4, LSEC), 128>>>(out, BATCH);
        else
            shrink_kernel<<<dim3(4, LSEC), 128>>>(sb, LDP);
    }
}